// round 2
// baseline (speedup 1.0000x reference)
#include <cuda_runtime.h>
#include <cuda_bf16.h>

// Problem constants (fixed shapes for this problem instance)
#define NN   50000
#define NE   1600000
#define TT   (NE + NN)      // edges + self loops
#define INCH 256
#define HID  64
#define LAT  32
#define GATH 32
#define OUTC 256

// ---------------------------------------------------------------------------
// Device scratch (static allocation only — no cudaMalloc allowed)
// ---------------------------------------------------------------------------
__device__ __align__(128) float g_bufH[NN * 64];    // pre-BN activations
__device__ __align__(128) float g_bufR[NN * 64];    // post-BN activations (r1, r2)
__device__ __align__(128) float g_r3[NN * 32];      // MLP branch output
__device__ __align__(128) float g_hg[NN * 32];      // GAT transformed features (h = x@W)
__device__ __align__(128) float g_gh[NN * 32];      // relu(gat_out + b)
__device__ __align__(128) float g_hf[NN * 32];      // GAT branch final
__device__ __align__(128) float g_gout[NN * 32];    // GAT aggregation accumulator
__device__ __align__(128) float g_s[NN];
__device__ __align__(128) float g_d[NN];
__device__ __align__(128) unsigned g_mmax[NN];
__device__ __align__(128) float g_den[NN];
__device__ __align__(128) float g_ex[TT];
__device__ float g_colsum[64];
__device__ float g_colsq[64];
__device__ float g_scale[64];
__device__ float g_shift[64];

// ---------------------------------------------------------------------------
// Generic tiled fp32 GEMM:  C[N,F] = act(A[N,K] @ W[K,F] + bias)
// Tile: 64 rows x FT cols, K in chunks of 32. 256 threads.
// BLEND: A := 0.5*(A + A2) on the fly (for final blended GEMM).
// ---------------------------------------------------------------------------
template<int FT, bool RELU, bool BLEND>
__global__ __launch_bounds__(256) void gemm_k(
    const float* __restrict__ A, const float* __restrict__ A2,
    const float* __restrict__ W, const float* __restrict__ bias,
    float* __restrict__ C, int N, int K, int F)
{
    __shared__ float Ash[64][33];
    __shared__ float Wsh[32][FT + 1];
    const int rbase = blockIdx.x * 64;
    const int cbase = blockIdx.y * FT;
    const int tid = threadIdx.x;
    constexpr int CPT = FT / 4;

    float acc[CPT];
#pragma unroll
    for (int j = 0; j < CPT; j++) acc[j] = 0.f;

    const int row = tid >> 2;
    const int cg = tid & 3;

    for (int k0 = 0; k0 < K; k0 += 32) {
        // A tile: 64x32, coalesced
#pragma unroll
        for (int p = 0; p < 8; p++) {
            int idx = tid + p * 256;
            int r = idx >> 5, c = idx & 31;
            int gr = rbase + r;
            float v = 0.f;
            if (gr < N) {
                v = A[(long)gr * K + k0 + c];
                if (BLEND) v = 0.5f * (v + A2[(long)gr * K + k0 + c]);
            }
            Ash[r][c] = v;
        }
        // W tile: 32xFT
#pragma unroll
        for (int idx = tid; idx < 32 * FT; idx += 256) {
            int r = idx / FT, c = idx % FT;
            Wsh[r][c] = W[(long)(k0 + r) * F + cbase + c];
        }
        __syncthreads();
#pragma unroll
        for (int kk = 0; kk < 32; kk++) {
            float a = Ash[row][kk];
#pragma unroll
            for (int j = 0; j < CPT; j++)
                acc[j] = fmaf(a, Wsh[kk][cg * CPT + j], acc[j]);
        }
        __syncthreads();
    }

    int gr = rbase + row;
    if (gr < N) {
#pragma unroll
        for (int j = 0; j < CPT; j++) {
            int c = cbase + cg * CPT + j;
            float v = acc[j];
            if (bias) v += bias[c];
            if (RELU) v = fmaxf(v, 0.f);
            C[(long)gr * F + c] = v;
        }
    }
}

// ---------------------------------------------------------------------------
// BatchNorm helpers
// ---------------------------------------------------------------------------
__global__ void zstats_k() {
    int i = threadIdx.x;
    if (i < 64) { g_colsum[i] = 0.f; g_colsq[i] = 0.f; }
}

__global__ __launch_bounds__(256) void colstats_k(const float* __restrict__ H, int N, int C) {
    __shared__ float ss[64], sq[64];
    int tid = threadIdx.x;
    if (tid < C) { ss[tid] = 0.f; sq[tid] = 0.f; }
    __syncthreads();
    int lanes = 256 / C;
    int c = tid % C;
    int rl = tid / C;
    float s = 0.f, q = 0.f;
    for (int r = blockIdx.x * lanes + rl; r < N; r += gridDim.x * lanes) {
        float v = H[(long)r * C + c];
        s += v; q += v * v;
    }
    atomicAdd(&ss[c], s);
    atomicAdd(&sq[c], q);
    __syncthreads();
    if (tid < C) { atomicAdd(&g_colsum[tid], ss[tid]); atomicAdd(&g_colsq[tid], sq[tid]); }
}

__global__ void bnprep_k(const float* __restrict__ g, const float* __restrict__ be, int C) {
    int c = threadIdx.x;
    if (c < C) {
        float invN = 1.0f / (float)NN;
        float m = g_colsum[c] * invN;
        float v = g_colsq[c] * invN - m * m;
        float sc = g[c] * rsqrtf(v + 1e-5f);
        g_scale[c] = sc;
        g_shift[c] = be[c] - m * sc;
    }
}

__global__ __launch_bounds__(256) void bnapply_k(const float* __restrict__ H, float* __restrict__ R,
                                                 int total, int Cmask) {
    int i = blockIdx.x * blockDim.x + threadIdx.x;
    if (i < total) {
        int c = i & Cmask;
        R[i] = fmaxf(fmaf(H[i], g_scale[c], g_shift[c]), 0.f);
    }
}

// ---------------------------------------------------------------------------
// GAT kernels
// ---------------------------------------------------------------------------
__global__ __launch_bounds__(256) void sd_k(const float* __restrict__ Hg,
                                            const float* __restrict__ as_,
                                            const float* __restrict__ ad_) {
    int i = blockIdx.x * blockDim.x + threadIdx.x;
    if (i < NN) {
        float ss = 0.f, dd = 0.f;
#pragma unroll
        for (int k = 0; k < 32; k++) {
            float v = Hg[i * 32 + k];
            ss += v * as_[k];
            dd += v * ad_[k];
        }
        g_s[i] = ss;
        g_d[i] = dd;
    }
}

__global__ __launch_bounds__(256) void gatinit_k() {
    int i = blockIdx.x * blockDim.x + threadIdx.x;
    if (i < NN * 32) g_gout[i] = 0.f;
    if (i < NN) { g_den[i] = 0.f; g_mmax[i] = 0u; }
}

__device__ __forceinline__ unsigned enc_f(float f) {
    unsigned u = __float_as_uint(f);
    return (u & 0x80000000u) ? ~u : (u | 0x80000000u);
}
__device__ __forceinline__ float dec_f(unsigned u) {
    return (u & 0x80000000u) ? __uint_as_float(u ^ 0x80000000u) : __uint_as_float(~u);
}

__device__ __forceinline__ void edge_sd(const int* __restrict__ ei, int t, int& src, int& dst) {
    if (t < NE) { src = ei[t]; dst = ei[NE + t]; }
    else { src = dst = t - NE; }
}

__global__ __launch_bounds__(256) void edgemax_k(const int* __restrict__ ei) {
    int t = blockIdx.x * blockDim.x + threadIdx.x;
    if (t >= TT) return;
    int src, dst; edge_sd(ei, t, src, dst);
    float e = g_s[src] + g_d[dst];
    e = e > 0.f ? e : 0.2f * e;
    atomicMax(&g_mmax[dst], enc_f(e));
}

__global__ __launch_bounds__(256) void edgeexp_k(const int* __restrict__ ei) {
    int t = blockIdx.x * blockDim.x + threadIdx.x;
    if (t >= TT) return;
    int src, dst; edge_sd(ei, t, src, dst);
    float e = g_s[src] + g_d[dst];
    e = e > 0.f ? e : 0.2f * e;
    float m = dec_f(g_mmax[dst]);
    float ex = expf(e - m);
    g_ex[t] = ex;
    atomicAdd(&g_den[dst], ex);
}

__global__ __launch_bounds__(256) void edgeagg_k(const int* __restrict__ ei,
                                                 const float* __restrict__ Hg) {
    int t = blockIdx.x * blockDim.x + threadIdx.x;
    if (t >= TT) return;
    int src, dst; edge_sd(ei, t, src, dst);
    float alpha = g_ex[t] / g_den[dst];
    const float4* h4 = reinterpret_cast<const float4*>(Hg + (long)src * 32);
    float* outp = g_gout + (long)dst * 32;
#pragma unroll
    for (int j = 0; j < 8; j++) {
        float4 v = h4[j];
        asm volatile("red.global.add.v4.f32 [%0], {%1,%2,%3,%4};"
                     :: "l"(outp + j * 4),
                        "f"(alpha * v.x), "f"(alpha * v.y),
                        "f"(alpha * v.z), "f"(alpha * v.w)
                     : "memory");
    }
}

__global__ __launch_bounds__(256) void biasrelu_k(const float* __restrict__ H,
                                                  const float* __restrict__ b,
                                                  float* __restrict__ R, int total) {
    int i = blockIdx.x * blockDim.x + threadIdx.x;
    if (i < total) R[i] = fmaxf(H[i] + b[i & 31], 0.f);
}

// ---------------------------------------------------------------------------
// Launch orchestration
// ---------------------------------------------------------------------------
static float* dev_ptr(float* sym_addr) { return sym_addr; }

extern "C" void kernel_launch(void* const* d_in, const int* in_sizes, int n_in,
                              void* d_out, int out_size)
{
    const float* x     = (const float*)d_in[0];
    const int*   ei    = (const int*)  d_in[1];
    const float* W_g1  = (const float*)d_in[2];
    const float* as_g1 = (const float*)d_in[3];
    const float* ad_g1 = (const float*)d_in[4];
    const float* b_g1  = (const float*)d_in[5];
    const float* W_g2  = (const float*)d_in[6];
    const float* as_g2 = (const float*)d_in[7];
    const float* ad_g2 = (const float*)d_in[8];
    const float* b_g2  = (const float*)d_in[9];
    const float* W_gf  = (const float*)d_in[10];
    const float* b_gf  = (const float*)d_in[11];
    const float* W_m1  = (const float*)d_in[12];
    const float* b_m1  = (const float*)d_in[13];
    const float* g_m1  = (const float*)d_in[14];
    const float* be_m1 = (const float*)d_in[15];
    const float* W_m2  = (const float*)d_in[16];
    const float* b_m2  = (const float*)d_in[17];
    const float* g_m2  = (const float*)d_in[18];
    const float* be_m2 = (const float*)d_in[19];
    const float* W_m3  = (const float*)d_in[20];
    const float* b_m3  = (const float*)d_in[21];
    const float* g_m3  = (const float*)d_in[22];
    const float* be_m3 = (const float*)d_in[23];
    const float* W_f   = (const float*)d_in[24];
    const float* b_f   = (const float*)d_in[25];
    float* out = (float*)d_out;

    // Resolve device symbol addresses (host side; no allocation)
    float *bufH, *bufR, *r3, *hg, *gh, *hf;
    cudaGetSymbolAddress((void**)&bufH, g_bufH);
    cudaGetSymbolAddress((void**)&bufR, g_bufR);
    cudaGetSymbolAddress((void**)&r3,   g_r3);
    cudaGetSymbolAddress((void**)&hg,   g_hg);
    cudaGetSymbolAddress((void**)&gh,   g_gh);
    cudaGetSymbolAddress((void**)&hf,   g_hf);

    const int GROWS = (NN + 63) / 64;     // 782
    const int EBLK  = (TT + 255) / 256;   // edge-kernel blocks
    const int NBLK  = (NN + 255) / 256;
    const int NB32  = (NN * 32 + 255) / 256;
    const int NB64  = (NN * 64 + 255) / 256;

    // ================= MLP branch =================
    // Layer 1: x[50000,256] @ W_m1[256,64] -> BN -> ReLU
    zstats_k<<<1, 64>>>();
    gemm_k<64, false, false><<<dim3(GROWS, 1), 256>>>(x, nullptr, W_m1, b_m1, bufH, NN, INCH, HID);
    colstats_k<<<160, 256>>>(bufH, NN, 64);
    bnprep_k<<<1, 64>>>(g_m1, be_m1, 64);
    bnapply_k<<<NB64, 256>>>(bufH, bufR, NN * 64, 63);
    // Layer 2: 64 -> 64
    zstats_k<<<1, 64>>>();
    gemm_k<64, false, false><<<dim3(GROWS, 1), 256>>>(bufR, nullptr, W_m2, b_m2, bufH, NN, HID, HID);
    colstats_k<<<160, 256>>>(bufH, NN, 64);
    bnprep_k<<<1, 64>>>(g_m2, be_m2, 64);
    bnapply_k<<<NB64, 256>>>(bufH, bufR, NN * 64, 63);
    // Layer 3: 64 -> 32
    zstats_k<<<1, 64>>>();
    gemm_k<32, false, false><<<dim3(GROWS, 1), 256>>>(bufR, nullptr, W_m3, b_m3, bufH, NN, HID, LAT);
    colstats_k<<<160, 256>>>(bufH, NN, 32);
    bnprep_k<<<1, 64>>>(g_m3, be_m3, 32);
    bnapply_k<<<NB32, 256>>>(bufH, r3, NN * 32, 31);

    // ================= GAT branch =================
    // Layer 1: h = x @ W_g1
    gemm_k<32, false, false><<<dim3(GROWS, 1), 256>>>(x, nullptr, W_g1, nullptr, hg, NN, INCH, GATH);
    sd_k<<<NBLK, 256>>>(hg, as_g1, ad_g1);
    gatinit_k<<<NB32, 256>>>();
    edgemax_k<<<EBLK, 256>>>(ei);
    edgeexp_k<<<EBLK, 256>>>(ei);
    edgeagg_k<<<EBLK, 256>>>(ei, hg);
    {
        float* goutp; cudaGetSymbolAddress((void**)&goutp, g_gout);
        biasrelu_k<<<NB32, 256>>>(goutp, b_g1, gh, NN * 32);
    }
    // Layer 2: h = gh @ W_g2
    gemm_k<32, false, false><<<dim3(GROWS, 1), 256>>>(gh, nullptr, W_g2, nullptr, hg, NN, GATH, GATH);
    sd_k<<<NBLK, 256>>>(hg, as_g2, ad_g2);
    gatinit_k<<<NB32, 256>>>();
    edgemax_k<<<EBLK, 256>>>(ei);
    edgeexp_k<<<EBLK, 256>>>(ei);
    edgeagg_k<<<EBLK, 256>>>(ei, hg);
    {
        float* goutp; cudaGetSymbolAddress((void**)&goutp, g_gout);
        biasrelu_k<<<NB32, 256>>>(goutp, b_g2, gh, NN * 32);
    }
    // Final GAT linear: hf = gh @ W_gf + b_gf
    gemm_k<32, false, false><<<dim3(GROWS, 1), 256>>>(gh, nullptr, W_gf, b_gf, hf, NN, GATH, LAT);

    // ================= Final blend + linear + ReLU =================
    // out = relu( (0.5*r3 + 0.5*hf) @ W_f + b_f )   [50000, 256]
    gemm_k<64, true, true><<<dim3(GROWS, 4), 256>>>(r3, hf, W_f, b_f, out, NN, LAT, OUTC);
}

// round 3
// speedup vs baseline: 1.3893x; 1.3893x over previous
#include <cuda_runtime.h>

// Problem constants
#define NN   50000
#define NE   1600000
#define TT   (NE + NN)       // edges + self loops
#define INCH 256
#define HID  64
#define LAT  32
#define GATH 32
#define OUTC 256
#define NPART 196            // ceil(NN/256)

// ---------------------------------------------------------------------------
// Device scratch (static only)
// ---------------------------------------------------------------------------
__device__ __align__(128) float g_H1[NN * 64];   // pre-BN layer1
__device__ __align__(128) float g_H2[NN * 64];   // pre-BN layer2
__device__ __align__(128) float g_H3[NN * 32];   // pre-BN layer3
__device__ __align__(128) float g_hg[NN * 32];   // GAT h = A @ W
__device__ __align__(128) float g_gh[NN * 32];   // GAT aggregated + bias + relu
__device__ __align__(128) float g_hf[NN * 32];   // GAT branch final
__device__ __align__(128) float g_s[NN];
__device__ __align__(128) float g_d[NN];
__device__ __align__(128) int   g_deg[NN];
__device__ __align__(128) int   g_rowoff[NN];
__device__ __align__(128) int   g_cursor[NN];
__device__ __align__(128) int   g_csr[TT];
__device__ int   g_partial[256];
__device__ float g_colsum[64], g_colsq[64];
__device__ float g_scale[64], g_shift[64];

// ---------------------------------------------------------------------------
// f32x2 packed-FMA helpers (sm_103a FFMA2 path — PTX only)
// ---------------------------------------------------------------------------
typedef unsigned long long u64;
__device__ __forceinline__ u64 pack2(float a, float b) {
    u64 r; asm("mov.b64 %0,{%1,%2};" : "=l"(r) : "f"(a), "f"(b)); return r;
}
__device__ __forceinline__ void fma2(u64& d, u64 a, u64 b) {
    asm("fma.rn.f32x2 %0, %1, %2, %0;" : "+l"(d) : "l"(a), "l"(b));
}
__device__ __forceinline__ void unpk2(u64 v, float& x, float& y) {
    asm("mov.b64 {%0,%1},%2;" : "=f"(x), "=f"(y) : "l"(v));
}

// ---------------------------------------------------------------------------
// Fused tiled GEMM:  C[N,F] = act(load(A)[N,K] @ W[K,F] + bias)
//   BNIN : A-load applies y = relu(A*scale[k]+shift[k])   (prev layer BN)
//   BLEND: A-load then v = 0.5*(v + A2)                    (final blend)
//   STATS: epilogue accumulates column sum/sumsq of C (pre-ReLU, post-bias)
//   SD   : epilogue computes per-row dots with as_/ad_ -> g_s/g_d
// Tile 64 rows x FT cols, K chunks of 32, 256 threads.
// ---------------------------------------------------------------------------
template<int FT, bool RELU, bool BLEND, bool BNIN, bool STATS, bool SD>
__global__ __launch_bounds__(256) void gemm_k(
    const float* __restrict__ A, const float* __restrict__ A2,
    const float* __restrict__ W, const float* __restrict__ bias,
    const float* __restrict__ as_, const float* __restrict__ ad_,
    float* __restrict__ C, int N, int K, int F)
{
    __shared__ __align__(16) float Ash[64][33];
    __shared__ __align__(16) float Wsh[32][FT];
    __shared__ float s_sum[FT], s_sq[FT];

    const int tid   = threadIdx.x;
    const int rbase = blockIdx.x * 64;
    const int cbase = blockIdx.y * FT;
    constexpr int CPT = FT / 4;
    constexpr int CP2 = CPT / 2;
    const int row = tid >> 2, cg = tid & 3;

    if (STATS && tid < FT) { s_sum[tid] = 0.f; s_sq[tid] = 0.f; }

    u64 acc2[CP2];
#pragma unroll
    for (int j = 0; j < CP2; j++) acc2[j] = 0ull;

    for (int k0 = 0; k0 < K; k0 += 32) {
#pragma unroll
        for (int p = 0; p < 8; p++) {
            int idx = tid + p * 256;
            int r = idx >> 5, c = idx & 31;
            int gr = rbase + r;
            float v = 0.f;
            if (gr < N) {
                v = A[(long)gr * K + k0 + c];
                if (BNIN) { int kc = k0 + c; v = fmaxf(fmaf(v, g_scale[kc], g_shift[kc]), 0.f); }
                if (BLEND) v = 0.5f * (v + A2[(long)gr * K + k0 + c]);
            }
            Ash[r][c] = v;
        }
#pragma unroll
        for (int idx = tid; idx < 32 * FT; idx += 256) {
            int r = idx / FT, c = idx % FT;
            Wsh[r][c] = W[(long)(k0 + r) * F + cbase + c];
        }
        __syncthreads();
#pragma unroll
        for (int kk = 0; kk < 32; kk++) {
            float a = Ash[row][kk];
            u64 a2 = pack2(a, a);
            const u64* wr = reinterpret_cast<const u64*>(&Wsh[kk][cg * CPT]);
#pragma unroll
            for (int j = 0; j < CP2; j++) fma2(acc2[j], a2, wr[j]);
        }
        __syncthreads();
    }

    float av[CPT];
#pragma unroll
    for (int j = 0; j < CP2; j++) unpk2(acc2[j], av[2 * j], av[2 * j + 1]);

    int gr = rbase + row;
    bool valid = gr < N;

    if (SD) {
        float sp = 0.f, dp = 0.f;
#pragma unroll
        for (int j = 0; j < CPT; j++) {
            float h = av[j];
            sp = fmaf(h, as_[cg * CPT + j], sp);
            dp = fmaf(h, ad_[cg * CPT + j], dp);
        }
        sp += __shfl_xor_sync(0xffffffffu, sp, 1);
        dp += __shfl_xor_sync(0xffffffffu, dp, 1);
        sp += __shfl_xor_sync(0xffffffffu, sp, 2);
        dp += __shfl_xor_sync(0xffffffffu, dp, 2);
        if (cg == 0 && valid) { g_s[gr] = sp; g_d[gr] = dp; }
    }

#pragma unroll
    for (int j = 0; j < CPT; j++) {
        int c = cbase + cg * CPT + j;
        float v = av[j];
        if (bias) v += bias[c];
        if (STATS) {
            float sv = valid ? v : 0.f;
            float sq = sv * sv;
#pragma unroll
            for (int o = 16; o >= 4; o >>= 1) {
                sv += __shfl_down_sync(0xffffffffu, sv, o);
                sq += __shfl_down_sync(0xffffffffu, sq, o);
            }
            if ((tid & 31) < 4) {
                atomicAdd(&s_sum[cg * CPT + j], sv);
                atomicAdd(&s_sq[cg * CPT + j], sq);
            }
        }
        if (RELU) v = fmaxf(v, 0.f);
        if (valid) C[(long)gr * F + c] = v;
    }

    if (STATS) {
        __syncthreads();
        if (tid < FT) {
            atomicAdd(&g_colsum[tid], s_sum[tid]);
            atomicAdd(&g_colsq[tid], s_sq[tid]);
        }
    }
}

// ---------------------------------------------------------------------------
// BatchNorm prep: scale/shift from accumulated stats; self-zeroes stats.
// ---------------------------------------------------------------------------
__global__ void bnprep_k(const float* __restrict__ g, const float* __restrict__ be, int Cc) {
    int c = threadIdx.x;
    if (c < Cc) {
        float invN = 1.0f / (float)NN;
        float m = g_colsum[c] * invN;
        float v = g_colsq[c] * invN - m * m;
        float sc = g[c] * rsqrtf(v + 1e-5f);
        g_scale[c] = sc;
        g_shift[c] = fmaf(-m, sc, be[c]);
    }
    if (c < 64) { g_colsum[c] = 0.f; g_colsq[c] = 0.f; }
}

// ---------------------------------------------------------------------------
// CSR build (per launch — deterministic work, order-only nondeterminism)
// ---------------------------------------------------------------------------
__global__ void init_k() {
    int i = blockIdx.x * 256 + threadIdx.x;
    if (i < NN) g_deg[i] = 0;
    if (i < 64) { g_colsum[i] = 0.f; g_colsq[i] = 0.f; }
}

__global__ __launch_bounds__(256) void hist_k(const int* __restrict__ ei) {
    int t = blockIdx.x * 256 + threadIdx.x;
    if (t >= TT) return;
    int dst = (t < NE) ? ei[NE + t] : (t - NE);
    atomicAdd(&g_deg[dst], 1);
}

__global__ __launch_bounds__(256) void scan1_k() {
    __shared__ int ws[9];
    int t = threadIdx.x, b = blockIdx.x;
    int i = b * 256 + t;
    int v = (i < NN) ? g_deg[i] : 0;
    int lane = t & 31, wid = t >> 5;
    int x = v;
#pragma unroll
    for (int o = 1; o < 32; o <<= 1) {
        int y = __shfl_up_sync(0xffffffffu, x, o);
        if (lane >= o) x += y;
    }
    if (lane == 31) ws[wid] = x;
    __syncthreads();
    if (t == 0) {
        int s = 0;
        for (int w = 0; w < 8; w++) { int tmp = ws[w]; ws[w] = s; s += tmp; }
        ws[8] = s;
    }
    __syncthreads();
    int excl = x - v + ws[wid];
    if (i < NN) g_rowoff[i] = excl;
    if (t == 0) g_partial[b] = ws[8];
}

__global__ __launch_bounds__(256) void scan2_k() {
    __shared__ int ws[9];
    int t = threadIdx.x;
    int v = (t < NPART) ? g_partial[t] : 0;
    int lane = t & 31, wid = t >> 5;
    int x = v;
#pragma unroll
    for (int o = 1; o < 32; o <<= 1) {
        int y = __shfl_up_sync(0xffffffffu, x, o);
        if (lane >= o) x += y;
    }
    if (lane == 31) ws[wid] = x;
    __syncthreads();
    if (t == 0) {
        int s = 0;
        for (int w = 0; w < 8; w++) { int tmp = ws[w]; ws[w] = s; s += tmp; }
        ws[8] = s;
    }
    __syncthreads();
    if (t < NPART) g_partial[t] = x - v + ws[wid];
}

__global__ void scan3_k() {
    int i = blockIdx.x * 256 + threadIdx.x;
    if (i < NN) {
        int off = g_rowoff[i] + g_partial[i >> 8];
        g_rowoff[i] = off;
        g_cursor[i] = off;
    }
}

__global__ __launch_bounds__(256) void scatter_k(const int* __restrict__ ei) {
    int t = blockIdx.x * 256 + threadIdx.x;
    if (t >= TT) return;
    int src, dst;
    if (t < NE) { src = ei[t]; dst = ei[NE + t]; }
    else        { src = dst = t - NE; }
    int p = atomicAdd(&g_cursor[dst], 1);
    g_csr[p] = src;
}

// ---------------------------------------------------------------------------
// GAT softmax-aggregate: warp per dst node, no atomics.
//   out[dst,f] = relu( (sum_j exp(e_j) * h[src_j, f]) / (sum_j exp(e_j)) + b[f] )
// exp without max-subtraction: algebraically identical softmax, e bounded.
// ---------------------------------------------------------------------------
__global__ __launch_bounds__(256) void agg_k(const float* __restrict__ Hg,
                                             const float* __restrict__ bias,
                                             float* __restrict__ outR) {
    int w = (blockIdx.x * 256 + threadIdx.x) >> 5;
    int lane = threadIdx.x & 31;
    if (w >= NN) return;
    int beg = g_rowoff[w];
    int n   = g_deg[w];
    float dd = g_d[w];
    float acc = 0.f, den = 0.f;
    for (int p0 = 0; p0 < n; p0 += 32) {
        int m = n - p0; if (m > 32) m = 32;
        int src = 0; float ex = 0.f;
        if (lane < m) {
            src = g_csr[beg + p0 + lane];
            float e = g_s[src] + dd;
            e = e > 0.f ? e : 0.2f * e;
            ex = __expf(e);
        }
        // fixed-trip loop -> unrolled, batched independent L2 gathers
#pragma unroll
        for (int j = 0; j < 32; j++) {
            float exj = __shfl_sync(0xffffffffu, ex, j);
            int   sj  = __shfl_sync(0xffffffffu, src, j);
            acc = fmaf(exj, Hg[sj * 32 + lane], acc);
            den += exj;
        }
    }
    outR[w * 32 + lane] = fmaxf(acc / den + bias[lane], 0.f);
}

// ---------------------------------------------------------------------------
// Orchestration
// ---------------------------------------------------------------------------
extern "C" void kernel_launch(void* const* d_in, const int* in_sizes, int n_in,
                              void* d_out, int out_size)
{
    const float* x     = (const float*)d_in[0];
    const int*   ei    = (const int*)  d_in[1];
    const float* W_g1  = (const float*)d_in[2];
    const float* as_g1 = (const float*)d_in[3];
    const float* ad_g1 = (const float*)d_in[4];
    const float* b_g1  = (const float*)d_in[5];
    const float* W_g2  = (const float*)d_in[6];
    const float* as_g2 = (const float*)d_in[7];
    const float* ad_g2 = (const float*)d_in[8];
    const float* b_g2  = (const float*)d_in[9];
    const float* W_gf  = (const float*)d_in[10];
    const float* b_gf  = (const float*)d_in[11];
    const float* W_m1  = (const float*)d_in[12];
    const float* b_m1  = (const float*)d_in[13];
    const float* g_m1  = (const float*)d_in[14];
    const float* be_m1 = (const float*)d_in[15];
    const float* W_m2  = (const float*)d_in[16];
    const float* b_m2  = (const float*)d_in[17];
    const float* g_m2  = (const float*)d_in[18];
    const float* be_m2 = (const float*)d_in[19];
    const float* W_m3  = (const float*)d_in[20];
    const float* b_m3  = (const float*)d_in[21];
    const float* g_m3  = (const float*)d_in[22];
    const float* be_m3 = (const float*)d_in[23];
    const float* W_f   = (const float*)d_in[24];
    const float* b_f   = (const float*)d_in[25];
    float* out = (float*)d_out;

    float *H1, *H2, *H3, *hg, *gh, *hf;
    cudaGetSymbolAddress((void**)&H1, g_H1);
    cudaGetSymbolAddress((void**)&H2, g_H2);
    cudaGetSymbolAddress((void**)&H3, g_H3);
    cudaGetSymbolAddress((void**)&hg, g_hg);
    cudaGetSymbolAddress((void**)&gh, g_gh);
    cudaGetSymbolAddress((void**)&hf, g_hf);

    const int GROWS = (NN + 63) / 64;
    const int EBLK  = (TT + 255) / 256;
    const int NBLK  = (NN + 255) / 256;
    const int ABLK  = (NN * 32 + 255) / 256;   // warp-per-node agg blocks

    // ---- CSR build (also zeroes BN stat accumulators) ----
    init_k<<<NBLK, 256>>>();
    hist_k<<<EBLK, 256>>>(ei);
    scan1_k<<<NPART, 256>>>();
    scan2_k<<<1, 256>>>();
    scan3_k<<<NBLK, 256>>>();
    scatter_k<<<EBLK, 256>>>(ei);

    // ---- MLP branch (BN stats fused into GEMM epilogue, BN-apply into next load) ----
    gemm_k<64, false, false, false, true, false><<<dim3(GROWS, 1), 256>>>(
        x, nullptr, W_m1, b_m1, nullptr, nullptr, H1, NN, INCH, HID);
    bnprep_k<<<1, 64>>>(g_m1, be_m1, 64);
    gemm_k<64, false, false, true, true, false><<<dim3(GROWS, 1), 256>>>(
        H1, nullptr, W_m2, b_m2, nullptr, nullptr, H2, NN, HID, HID);
    bnprep_k<<<1, 64>>>(g_m2, be_m2, 64);
    gemm_k<32, false, false, true, true, false><<<dim3(GROWS, 1), 256>>>(
        H2, nullptr, W_m3, b_m3, nullptr, nullptr, H3, NN, HID, LAT);
    bnprep_k<<<1, 64>>>(g_m3, be_m3, 32);

    // ---- GAT branch ----
    gemm_k<32, false, false, false, false, true><<<dim3(GROWS, 1), 256>>>(
        x, nullptr, W_g1, nullptr, as_g1, ad_g1, hg, NN, INCH, GATH);
    agg_k<<<ABLK, 256>>>(hg, b_g1, gh);
    gemm_k<32, false, false, false, false, true><<<dim3(GROWS, 1), 256>>>(
        gh, nullptr, W_g2, nullptr, as_g2, ad_g2, hg, NN, GATH, GATH);
    agg_k<<<ABLK, 256>>>(hg, b_g2, gh);
    gemm_k<32, false, false, false, false, false><<<dim3(GROWS, 1), 256>>>(
        gh, nullptr, W_gf, b_gf, nullptr, nullptr, hf, NN, GATH, LAT);

    // ---- Final: out = relu((0.5*bnrelu(H3) + 0.5*hf) @ W_f + b_f) ----
    gemm_k<64, true, true, true, false, false><<<dim3(GROWS, 4), 256>>>(
        H3, hf, W_f, b_f, nullptr, nullptr, out, NN, LAT, OUTC);
}